// round 4
// baseline (speedup 1.0000x reference)
#include <cuda_runtime.h>
#include <cstdint>

// Problem constants (match reference)
#define GRID_D    128
#define NUM_CELLS (128 * 128 * 128)
#define INV_CELL  64.0f

// ---------------------------------------------------------------------------
// Zero the output grid (harness poisons d_out with 0xAA).
// out has NUM_CELLS * 4 floats = NUM_CELLS float4's.
// ---------------------------------------------------------------------------
__global__ __launch_bounds__(256) void zero_grid_kernel(float4* __restrict__ out, int n4) {
    int i = blockIdx.x * blockDim.x + threadIdx.x;
    if (i < n4) {
        out[i] = make_float4(0.f, 0.f, 0.f, 0.f);
    }
}

// ---------------------------------------------------------------------------
// P2G scatter: each thread = one particle. Trilinear weights to the 8 corners
// of the enclosing cell; scatter (mass, mom.x, mom.y, mom.z) per corner with a
// single vector reduction red.global.add.v4.f32 (sm_90+), cutting atomic count
// 4x vs scalar atomicAdd.
//
// hash = z + x*128 + y*128*128  (z fastest). Positions are guaranteed one cell
// inside the boundary, so base in [1,126] and all 8 hashes are in range (the
// reference's valid-mask is always true for these inputs).
// ---------------------------------------------------------------------------
__global__ __launch_bounds__(256) void p2g_scatter_kernel(
    const float* __restrict__ pos,
    const float* __restrict__ vel,
    const float* __restrict__ mass,
    float4* __restrict__ out,
    int n)
{
    int i = blockIdx.x * blockDim.x + threadIdx.x;
    if (i >= n) return;

    const float px = pos[3 * i + 0];
    const float py = pos[3 * i + 1];
    const float pz = pos[3 * i + 2];
    const float vx = vel[3 * i + 0];
    const float vy = vel[3 * i + 1];
    const float vz = vel[3 * i + 2];
    const float m  = mass[i];

    // position in cell units
    const float rx = px * INV_CELL;
    const float ry = py * INV_CELL;
    const float rz = pz * INV_CELL;
    const float bx = floorf(rx);
    const float by = floorf(ry);
    const float bz = floorf(rz);
    const float fx = rx - bx;   // in [0,1)
    const float fy = ry - by;
    const float fz = rz - bz;

    const int ix = (int)bx;
    const int iy = (int)by;
    const int iz = (int)bz;

    // linear shape function weights per axis: offset 0 -> (1-f), offset 1 -> f
    const float wx[2] = { 1.f - fx, fx };
    const float wy[2] = { 1.f - fy, fy };
    const float wz[2] = { 1.f - fz, fz };

    const int base = iz + ix * GRID_D + iy * (GRID_D * GRID_D);

    #pragma unroll
    for (int a = 0; a < 2; ++a) {
        #pragma unroll
        for (int b = 0; b < 2; ++b) {
            const float wab = wx[a] * wy[b] * m;
            const int   hab = base + a * GRID_D + b * (GRID_D * GRID_D);
            // z innermost: the two targets are adjacent float4's (same L2 line)
            #pragma unroll
            for (int c = 0; c < 2; ++c) {
                const float s = wab * wz[c];
                float4* p = out + (hab + c);
                asm volatile(
                    "red.global.add.v4.f32 [%0], {%1, %2, %3, %4};"
                    :: "l"(p), "f"(s), "f"(s * vx), "f"(s * vy), "f"(s * vz)
                    : "memory");
            }
        }
    }
}

extern "C" void kernel_launch(void* const* d_in, const int* in_sizes, int n_in,
                              void* d_out, int out_size) {
    const float* pos  = (const float*)d_in[0];   // [N,3] f32
    const float* vel  = (const float*)d_in[1];   // [N,3] f32
    const float* mass = (const float*)d_in[2];   // [N]   f32
    float4* out = (float4*)d_out;                // [NUM_CELLS, 4] f32

    const int n = in_sizes[2];                   // particle count (mass is [N])
    const int n4 = out_size / 4;                 // number of float4 rows

    // 1) zero the grid
    {
        int threads = 256;
        int blocks = (n4 + threads - 1) / threads;
        zero_grid_kernel<<<blocks, threads>>>(out, n4);
    }
    // 2) scatter
    {
        int threads = 256;
        int blocks = (n + threads - 1) / threads;
        p2g_scatter_kernel<<<blocks, threads>>>(pos, vel, mass, out, n);
    }
}

// round 7
// speedup vs baseline: 1.1097x; 1.1097x over previous
#include <cuda_runtime.h>
#include <cstdint>

// Problem constants (match reference)
#define GRID_D    128
#define NUM_CELLS (128 * 128 * 128)
#define INV_CELL  64.0f

// ---------------------------------------------------------------------------
// Zero the output grid (harness poisons d_out with 0xAA).
// ---------------------------------------------------------------------------
__global__ __launch_bounds__(256) void zero_grid_kernel(float4* __restrict__ out, int n4) {
    int i = blockIdx.x * blockDim.x + threadIdx.x;
    if (i < n4) {
        out[i] = make_float4(0.f, 0.f, 0.f, 0.f);
    }
}

// ---------------------------------------------------------------------------
// P2G scatter, transposed mapping: one thread = one (particle, corner) pair.
// 8 consecutive threads handle the 8 corners of one particle, so within a
// single red.global.add.v4.f32 instruction, lane pairs (2k, 2k+1) target
// ADJACENT float4's (the z-pair of a corner column) — same 32B sector, same
// 128B L2 line. This lets the L1TEX/LTS merge same-line lanes into one
// wavefront, halving LTS atomic wavefronts vs the 1-thread-per-particle
// formulation (where every lane of every RED hits a random line).
//
// Corner index c: bit2 = x-offset, bit1 = y, bit0 = z (matches FWD_WINDOW).
// hash = z + x*128 + y*128*128. Particles sit >= 1 cell inside the boundary,
// so all 8 hashes are in range (reference valid-mask always true here).
//
// Input loads are 8-way redundant across the corner lanes but consecutive
// lanes read identical addresses -> L1 broadcast; DRAM traffic unchanged.
// ---------------------------------------------------------------------------
__global__ __launch_bounds__(256) void p2g_scatter8_kernel(
    const float* __restrict__ pos,
    const float* __restrict__ vel,
    const float* __restrict__ mass,
    float4* __restrict__ out,
    int n8)
{
    int t = blockIdx.x * blockDim.x + threadIdx.x;
    if (t >= n8) return;

    const int p = t >> 3;      // particle index
    const int c = t & 7;       // corner index

    // position in cell units
    const float rx = pos[3 * p + 0] * INV_CELL;
    const float ry = pos[3 * p + 1] * INV_CELL;
    const float rz = pos[3 * p + 2] * INV_CELL;
    const float bx = floorf(rx);
    const float by = floorf(ry);
    const float bz = floorf(rz);
    const float fx = rx - bx;
    const float fy = ry - by;
    const float fz = rz - bz;

    const int ox = (c >> 2) & 1;
    const int oy = (c >> 1) & 1;
    const int oz = c & 1;

    const float wxv = ox ? fx : (1.f - fx);
    const float wyv = oy ? fy : (1.f - fy);
    const float wzv = oz ? fz : (1.f - fz);

    const float m = mass[p];
    const float s = wxv * wyv * wzv * m;

    const float vx = vel[3 * p + 0];
    const float vy = vel[3 * p + 1];
    const float vz = vel[3 * p + 2];

    const int h = ((int)bz + oz)
                + ((int)bx + ox) * GRID_D
                + ((int)by + oy) * (GRID_D * GRID_D);

    float4* q = out + h;
    asm volatile(
        "red.global.add.v4.f32 [%0], {%1, %2, %3, %4};"
        :: "l"(q), "f"(s), "f"(s * vx), "f"(s * vy), "f"(s * vz)
        : "memory");
}

extern "C" void kernel_launch(void* const* d_in, const int* in_sizes, int n_in,
                              void* d_out, int out_size) {
    const float* pos  = (const float*)d_in[0];   // [N,3] f32
    const float* vel  = (const float*)d_in[1];   // [N,3] f32
    const float* mass = (const float*)d_in[2];   // [N]   f32
    float4* out = (float4*)d_out;                // [NUM_CELLS, 4] f32

    const int n = in_sizes[2];                   // particle count (mass is [N])
    const int n4 = out_size / 4;                 // number of float4 rows

    // 1) zero the grid
    {
        int threads = 256;
        int blocks = (n4 + threads - 1) / threads;
        zero_grid_kernel<<<blocks, threads>>>(out, n4);
    }
    // 2) scatter: 8 threads per particle (one per stencil corner)
    {
        int threads = 256;
        long long n8 = (long long)n * 8;
        int blocks = (int)((n8 + threads - 1) / threads);
        p2g_scatter8_kernel<<<blocks, threads>>>(pos, vel, mass, out, (int)n8);
    }
}